// round 12
// baseline (speedup 1.0000x reference)
#include <cuda_runtime.h>
#include <cuda_fp16.h>
#include <cstdint>

#define Bn 16
#define Fn 257
#define FPAD 272
#define Tn 8000
#define NBn 64
#define TTILE 128
#define KSTEPS 17

// ---- scan config (r11 proven) ----
#define NCH 20
#define CHUNK 400
#define WARM 128
#define UNITS_PER_B 21                 // 21*256 = 5376 >= 257*20 threads
#define NSCAN (Bn * UNITS_PER_B)       // 336
#define NBAND (Bn * 63)                // 1008
#define NITEMS (NSCAN + NBAND)         // 1344
#define NGRID 296                      // 2 per SM, all resident wave-1

// ---- band GEMM config ----
#define AST 136
#define BST 280
#define OST 132
#define A_BYTES (FPAD * AST * 2)
#define B_BYTES (NBn * BST * 2)
#define SMEM_TOTAL (A_BYTES + B_BYTES)

// 65.8 MB fp16 scratch: g_vnr[b][f][t] = vnr/10 (t-contiguous)
__device__ __align__(128) __half g_vnr[(size_t)Bn * Fn * Tn];
__device__ __align__(128) __half g_fbh[NBn * BST];
__device__ int g_next;
__device__ int g_done[Bn];

struct __align__(16) H8 { __half2 a, b, c, d; };

__device__ __forceinline__ uint32_t smem_u32(const void* p) {
    uint32_t a;
    asm("{ .reg .u64 t; cvta.to.shared.u64 t, %1; cvt.u32.u64 %0, t; }" : "=r"(a) : "l"(p));
    return a;
}
__device__ __forceinline__ void cpasync16(uint32_t dst, const void* src, int sz) {
    asm volatile("cp.async.ca.shared.global [%0], [%1], 16, %2;" :: "r"(dst), "l"(src), "r"(sz));
}
__device__ __forceinline__ void cp_commit() { asm volatile("cp.async.commit_group;" ::: "memory"); }
__device__ __forceinline__ void cp_wait0()  { asm volatile("cp.async.wait_group 0;" ::: "memory"); }

__device__ __forceinline__ void ldsm_x4_t(uint32_t a[4], uint32_t addr) {
    asm volatile("ldmatrix.sync.aligned.m8n8.x4.trans.shared.b16 {%0,%1,%2,%3}, [%4];"
        : "=r"(a[0]), "=r"(a[1]), "=r"(a[2]), "=r"(a[3]) : "r"(addr));
}
__device__ __forceinline__ void ldsm_x4(uint32_t a[4], uint32_t addr) {
    asm volatile("ldmatrix.sync.aligned.m8n8.x4.shared.b16 {%0,%1,%2,%3}, [%4];"
        : "=r"(a[0]), "=r"(a[1]), "=r"(a[2]), "=r"(a[3]) : "r"(addr));
}
__device__ __forceinline__ void mma16816(float d[4], const uint32_t a[4], uint32_t b0, uint32_t b1) {
    asm volatile("mma.sync.aligned.m16n8k16.row.col.f32.f16.f16.f32 "
        "{%0,%1,%2,%3}, {%4,%5,%6,%7}, {%8,%9}, {%0,%1,%2,%3};"
        : "+f"(d[0]), "+f"(d[1]), "+f"(d[2]), "+f"(d[3])
        : "r"(a[0]), "r"(a[1]), "r"(a[2]), "r"(a[3]), "r"(b0), "r"(b1));
}
__device__ __forceinline__ float tanh_fast(float x) {
    float y; asm("tanh.approx.f32 %0, %1;" : "=f"(y) : "f"(x)); return y;
}

__device__ __forceinline__ float nf_step(float x, float nf, float rise, float fall, float fl) {
    float d  = x - nf;
    float cr = fmaf(rise, d, nf);
    float cf = fmaf(fall, d, nf);
    return fmaxf(fmaxf(cr, cf), fl);
}

// ============================================================
// Prelude: reset work counters (graph-replay safe) + fbconv
// ============================================================
__global__ __launch_bounds__(256) void prelude_kernel(const float* __restrict__ fbw)
{
    if (blockIdx.x == 0) {
        if (threadIdx.x == 0) g_next = 0;
        if (threadIdx.x < Bn) g_done[threadIdx.x] = 0;
        return;
    }
    int base = (blockIdx.x - 1) * 256 + threadIdx.x;
    for (int i = base; i < NBn * BST; i += 256 * 8) {
        int n = i / BST;
        int f = i - n * BST;
        g_fbh[i] = (f < Fn) ? __float2half_rn(__ldg(fbw + n * Fn + f)) : __float2half_rn(0.0f);
    }
}

// ============================================================
// scan unit (r11-proven body): one unit = 256 threads of batch b
// ============================================================
__device__ void scan_unit(int unit, int tid, const float* __restrict__ mag,
                          float rise, float fall, float ns10)
{
    const int b = unit / UNITS_PER_B;
    const int u = unit % UNITS_PER_B;
    const int ltid = u * 256 + tid;
    const int chunk = ltid % NCH;
    const int fidx  = ltid / NCH;
    if (fidx >= Fn) return;

    const size_t base = ((size_t)b * Fn + fidx) * Tn;
    const float4* gm = reinterpret_cast<const float4*>(mag + base);
    H8* gv8 = reinterpret_cast<H8*>(g_vnr + base);

    float mn = 3.4e38f;
    #pragma unroll
    for (int i = 0; i < 20; ++i) mn = fminf(mn, __ldg(mag + base + i));
    mn = fmaxf(mn, 1e-5f);
    const float fl = 0.5f * mn;
    float nf = mn;

    const int t0 = chunk * CHUNK;
    const int tw = (chunk == 0) ? 0 : (t0 - WARM);

    for (int q = (tw >> 2); q < (t0 >> 2); ++q) {
        float4 v = gm[q];
        nf = nf_step(v.x, nf, rise, fall, fl);
        nf = nf_step(v.y, nf, rise, fall, fl);
        nf = nf_step(v.z, nf, rise, fall, fl);
        nf = nf_step(v.w, nf, rise, fall, fl);
    }

    const int q0 = t0 >> 2;
    float4 b0 = gm[q0], b1 = gm[q0 + 1], b2 = gm[q0 + 2], b3 = gm[q0 + 3];

    #define EMIT8(ca, cb, idx8) { \
        float o0, o1, o2, o3, o4, o5, o6, o7; \
        nf = nf_step(ca.x, nf, rise, fall, fl); o0 = __fdividef(ca.x, fmaf(ns10, nf, 1e-7f)); \
        nf = nf_step(ca.y, nf, rise, fall, fl); o1 = __fdividef(ca.y, fmaf(ns10, nf, 1e-7f)); \
        nf = nf_step(ca.z, nf, rise, fall, fl); o2 = __fdividef(ca.z, fmaf(ns10, nf, 1e-7f)); \
        nf = nf_step(ca.w, nf, rise, fall, fl); o3 = __fdividef(ca.w, fmaf(ns10, nf, 1e-7f)); \
        nf = nf_step(cb.x, nf, rise, fall, fl); o4 = __fdividef(cb.x, fmaf(ns10, nf, 1e-7f)); \
        nf = nf_step(cb.y, nf, rise, fall, fl); o5 = __fdividef(cb.y, fmaf(ns10, nf, 1e-7f)); \
        nf = nf_step(cb.z, nf, rise, fall, fl); o6 = __fdividef(cb.z, fmaf(ns10, nf, 1e-7f)); \
        nf = nf_step(cb.w, nf, rise, fall, fl); o7 = __fdividef(cb.w, fmaf(ns10, nf, 1e-7f)); \
        H8 pk; \
        pk.a = __floats2half2_rn(o0, o1); pk.b = __floats2half2_rn(o2, o3); \
        pk.c = __floats2half2_rn(o4, o5); pk.d = __floats2half2_rn(o6, o7); \
        gv8[idx8] = pk; }

    for (int i = 0; i < CHUNK / 4; i += 4) {
        float4 c0 = b0, c1 = b1, c2 = b2, c3 = b3;
        if (i + 8 <= CHUNK / 4) {
            b0 = gm[q0 + i + 4]; b1 = gm[q0 + i + 5];
            b2 = gm[q0 + i + 6]; b3 = gm[q0 + i + 7];
        }
        EMIT8(c0, c1, (q0 + i) >> 1);
        EMIT8(c2, c3, ((q0 + i) >> 1) + 1);
    }
    #undef EMIT8
}

// ============================================================
// band unit (r11-proven body): one 128-t tile of batch b
// ============================================================
__device__ void band_unit(int b, int t0, int tid, char* f_smem, float* __restrict__ out)
{
    const int wid = tid >> 5;
    const int lane = tid & 31;

    __half* As = reinterpret_cast<__half*>(f_smem);
    __half* Bs = reinterpret_cast<__half*>(f_smem + A_BYTES);
    const uint32_t As_u = smem_u32(As);
    const uint32_t Bs_u = smem_u32(Bs);

    const size_t vbase = (size_t)b * Fn * Tn;
    #pragma unroll
    for (int it = 0; it < 17; ++it) {
        int i = tid + it * 256;
        int f = i >> 4;
        int c = i & 15;
        int t = t0 + c * 8;
        int sz = (f < Fn && t + 8 <= Tn) ? 16 : 0;
        int fc = (f < Fn) ? f : 0;
        int tc = (t + 8 <= Tn) ? t : 0;
        cpasync16(As_u + (uint32_t)((f * AST + c * 8) * 2),
                  g_vnr + vbase + (size_t)fc * Tn + tc, sz);
    }
    #pragma unroll
    for (int it = 0; it < 9; ++it) {
        int i = tid + it * 256;
        if (i < NBn * BST / 8)
            cpasync16(Bs_u + (uint32_t)(i * 16), g_fbh + i * 8, 16);
    }
    cp_commit();
    cp_wait0();
    __syncthreads();

    const int m0 = wid * 16;
    const int krow = (lane & 7) + ((lane >> 4) << 3);
    const int msel = ((lane >> 3) & 1) * 8;
    const uint32_t a_addr0 = As_u + (uint32_t)((krow * AST + m0 + msel) * 2);

    const int nrow = (lane & 7) + ((lane >> 4) << 3);
    const int ksel = ((lane >> 3) & 1) * 8;
    uint32_t b_addr0[4];
    #pragma unroll
    for (int j2 = 0; j2 < 4; ++j2)
        b_addr0[j2] = Bs_u + (uint32_t)(((j2 * 16 + nrow) * BST + ksel) * 2);

    float d[8][4];
    #pragma unroll
    for (int j = 0; j < 8; ++j)
        #pragma unroll
        for (int q = 0; q < 4; ++q) d[j][q] = 0.0f;

    for (int ks = 0; ks < KSTEPS; ++ks) {
        uint32_t a[4];
        ldsm_x4_t(a, a_addr0 + (uint32_t)(ks * 16 * AST * 2));
        #pragma unroll
        for (int j2 = 0; j2 < 4; ++j2) {
            uint32_t bbv[4];
            ldsm_x4(bbv, b_addr0[j2] + (uint32_t)(ks * 32));
            mma16816(d[j2 * 2],     a, bbv[0], bbv[1]);
            mma16816(d[j2 * 2 + 1], a, bbv[2], bbv[3]);
        }
    }

    __syncthreads();
    float* stg = reinterpret_cast<float*>(f_smem);
    const int g  = lane >> 2;
    const int tp = lane & 3;
    #pragma unroll
    for (int j = 0; j < 8; ++j) {
        int n = j * 8 + 2 * tp;
        int t = m0 + g;
        stg[n * OST + t]           = d[j][0];
        stg[(n + 1) * OST + t]     = d[j][1];
        stg[n * OST + t + 8]       = d[j][2];
        stg[(n + 1) * OST + t + 8] = d[j][3];
    }
    __syncthreads();

    const int tmax = Tn - t0;
    float* ob = out + (size_t)b * NBn * Tn + t0;
    #pragma unroll
    for (int it = 0; it < 8; ++it) {
        int idx = tid + it * 256;
        int n = idx >> 5;
        int c = (idx & 31) * 4;
        if (c < tmax) {
            float4 v = *reinterpret_cast<float4*>(stg + n * OST + c);
            v.x = tanh_fast(v.x); v.y = tanh_fast(v.y);
            v.z = tanh_fast(v.z); v.w = tanh_fast(v.w);
            *reinterpret_cast<float4*>(ob + (size_t)n * Tn + c) = v;
        }
    }
}

// ============================================================
// Fused persistent kernel: work-queue over scan units then band tiles.
// All NGRID blocks resident (2/SM); scan items precede band items in
// counter order, so band spins always have running producers.
// ============================================================
extern __shared__ char f_smem[];

__global__ __launch_bounds__(256, 2) void fused_kernel(
    const float* __restrict__ mag, float* __restrict__ out,
    const float* __restrict__ p_ns,
    const float* __restrict__ p_rr,
    const float* __restrict__ p_rf)
{
    __shared__ int s_item;
    const int tid = threadIdx.x;

    const float rise = 1.0f / (1.0f + expf(-__ldg(p_rr)));
    const float fall = 1.0f / (1.0f + expf(-__ldg(p_rf)));
    const float ns10 = 10.0f * fabsf(__ldg(p_ns));

    for (;;) {
        __syncthreads();                        // protect s_item / smem reuse
        if (tid == 0) s_item = atomicAdd(&g_next, 1);
        __syncthreads();
        const int item = s_item;
        if (item >= NITEMS) break;

        if (item < NSCAN) {
            scan_unit(item, tid, mag, rise, fall, ns10);
            __threadfence();                    // release this thread's STGs
            __syncthreads();
            if (tid == 0) atomicAdd(&g_done[item / UNITS_PER_B], 1);
        } else {
            const int it = item - NSCAN;
            const int b  = it / 63;
            const int t0 = (it % 63) * TTILE;
            if (tid == 0) {
                while (atomicAdd(&g_done[b], 0) < UNITS_PER_B) __nanosleep(128);
            }
            __syncthreads();
            __threadfence();                    // acquire
            band_unit(b, t0, tid, f_smem, out);
        }
    }
}

// ============================================================
extern "C" void kernel_launch(void* const* d_in, const int* in_sizes, int n_in,
                              void* d_out, int out_size)
{
    const float* mag = (const float*)d_in[0];
    const float* fb  = (const float*)d_in[1];
    const float* ns  = (const float*)d_in[2];
    const float* rr  = (const float*)d_in[3];
    const float* rf  = (const float*)d_in[4];
    float* out = (float*)d_out;

    cudaFuncSetAttribute(fused_kernel, cudaFuncAttributeMaxDynamicSharedMemorySize, SMEM_TOTAL);

    prelude_kernel<<<9, 256>>>(fb);
    fused_kernel<<<NGRID, 256, SMEM_TOTAL>>>(mag, out, ns, rr, rf);
}

// round 13
// speedup vs baseline: 1.5241x; 1.5241x over previous
#include <cuda_runtime.h>
#include <cuda_fp16.h>
#include <cstdint>

#define Bn 16
#define Fn 257
#define FPAD 272
#define Tn 8000
#define NBn 64
#define TTILE 128
#define KSTEPS 17

// ---- scan config ----
#define NCH 20
#define CHUNK 400
#define WARM 128
#define SCAN_THREADS (Bn * Fn * NCH)               // 82240
#define SCAN_BLOCKS ((SCAN_THREADS + 255) / 256)   // 322

// ---- band GEMM config ----
#define AST 136
#define BST 280
#define OST 132
#define A_BYTES (FPAD * AST * 2)
#define B_BYTES (NBn * BST * 2)
#define SMEM_TOTAL (A_BYTES + B_BYTES)
#define KSPLIT 9                                   // first cp.async group: k-steps 0..8 (f<144)

// 65.8 MB fp16 scratch (fits in L2): g_vnr[b][f][t] = vnr/10
__device__ __align__(128) __half g_vnr[(size_t)Bn * Fn * Tn];
__device__ __align__(128) __half g_fbh[NBn * BST];

struct __align__(16) H8 { __half2 a, b, c, d; };

__device__ __forceinline__ uint32_t smem_u32(const void* p) {
    uint32_t a;
    asm("{ .reg .u64 t; cvta.to.shared.u64 t, %1; cvt.u32.u64 %0, t; }" : "=r"(a) : "l"(p));
    return a;
}
// streaming (evict-first) float4 load — keeps g_vnr resident in L2
__device__ __forceinline__ float4 ldg_cs4(const float4* p) {
    float4 v;
    asm volatile("ld.global.cs.v4.f32 {%0,%1,%2,%3}, [%4];"
        : "=f"(v.x), "=f"(v.y), "=f"(v.z), "=f"(v.w) : "l"(p));
    return v;
}
__device__ __forceinline__ float ldg_cs(const float* p) {
    float v; asm volatile("ld.global.cs.f32 %0, [%1];" : "=f"(v) : "l"(p)); return v;
}
__device__ __forceinline__ void cpasync16(uint32_t dst, const void* src, int sz) {
    asm volatile("cp.async.ca.shared.global [%0], [%1], 16, %2;" :: "r"(dst), "l"(src), "r"(sz));
}
__device__ __forceinline__ void cp_commit() { asm volatile("cp.async.commit_group;" ::: "memory"); }
__device__ __forceinline__ void cp_wait0()  { asm volatile("cp.async.wait_group 0;" ::: "memory"); }
__device__ __forceinline__ void cp_wait1()  { asm volatile("cp.async.wait_group 1;" ::: "memory"); }

__device__ __forceinline__ void ldsm_x4_t(uint32_t a[4], uint32_t addr) {
    asm volatile("ldmatrix.sync.aligned.m8n8.x4.trans.shared.b16 {%0,%1,%2,%3}, [%4];"
        : "=r"(a[0]), "=r"(a[1]), "=r"(a[2]), "=r"(a[3]) : "r"(addr));
}
__device__ __forceinline__ void ldsm_x4(uint32_t a[4], uint32_t addr) {
    asm volatile("ldmatrix.sync.aligned.m8n8.x4.shared.b16 {%0,%1,%2,%3}, [%4];"
        : "=r"(a[0]), "=r"(a[1]), "=r"(a[2]), "=r"(a[3]) : "r"(addr));
}
__device__ __forceinline__ void mma16816(float d[4], const uint32_t a[4], uint32_t b0, uint32_t b1) {
    asm volatile("mma.sync.aligned.m16n8k16.row.col.f32.f16.f16.f32 "
        "{%0,%1,%2,%3}, {%4,%5,%6,%7}, {%8,%9}, {%0,%1,%2,%3};"
        : "+f"(d[0]), "+f"(d[1]), "+f"(d[2]), "+f"(d[3])
        : "r"(a[0]), "r"(a[1]), "r"(a[2]), "r"(a[3]), "r"(b0), "r"(b1));
}
__device__ __forceinline__ float tanh_fast(float x) {
    float y; asm("tanh.approx.f32 %0, %1;" : "=f"(y) : "f"(x)); return y;
}

__device__ __forceinline__ float nf_step(float x, float nf, float rise, float fall, float fl) {
    float d  = x - nf;
    float cr = fmaf(rise, d, nf);
    float cf = fmaf(fall, d, nf);
    return fmaxf(fmaxf(cr, cf), fl);
}

// ============================================================
// K1: chunked scan -> fp16 scratch [b][f][t] (vnr/10)
// mag reads are ld.global.cs (streaming) so the scratch stays in L2.
// Blocks >= SCAN_BLOCKS: fused fb conversion.
// ============================================================
__global__ __launch_bounds__(256) void scan_kernel(
    const float* __restrict__ mag,
    const float* __restrict__ fbw,
    const float* __restrict__ p_ns,
    const float* __restrict__ p_rr,
    const float* __restrict__ p_rf)
{
    if (blockIdx.x >= SCAN_BLOCKS) {
        int base = (blockIdx.x - SCAN_BLOCKS) * 256 + threadIdx.x;
        for (int i = base; i < NBn * BST; i += 256 * 8) {
            int n = i / BST;
            int f = i - n * BST;
            g_fbh[i] = (f < Fn) ? __float2half_rn(__ldg(fbw + n * Fn + f)) : __float2half_rn(0.0f);
        }
        return;
    }

    int tid = blockIdx.x * 256 + threadIdx.x;
    if (tid >= SCAN_THREADS) return;
    int chunk = tid % NCH;
    int chain = tid / NCH;

    const float rise = 1.0f / (1.0f + expf(-__ldg(p_rr)));
    const float fall = 1.0f / (1.0f + expf(-__ldg(p_rf)));
    const float ns10 = 10.0f * fabsf(__ldg(p_ns));

    size_t base = (size_t)chain * Tn;
    const float4* gm = reinterpret_cast<const float4*>(mag + base);
    H8* gv8 = reinterpret_cast<H8*>(g_vnr + base);

    float mn = 3.4e38f;
    #pragma unroll
    for (int i = 0; i < 20; ++i) mn = fminf(mn, ldg_cs(mag + base + i));
    mn = fmaxf(mn, 1e-5f);
    const float fl = 0.5f * mn;
    float nf = mn;

    const int t0 = chunk * CHUNK;
    const int tw = (chunk == 0) ? 0 : (t0 - WARM);

    for (int q = (tw >> 2); q < (t0 >> 2); ++q) {
        float4 v = ldg_cs4(gm + q);
        nf = nf_step(v.x, nf, rise, fall, fl);
        nf = nf_step(v.y, nf, rise, fall, fl);
        nf = nf_step(v.z, nf, rise, fall, fl);
        nf = nf_step(v.w, nf, rise, fall, fl);
    }

    const int q0 = t0 >> 2;
    float4 b0 = ldg_cs4(gm + q0), b1 = ldg_cs4(gm + q0 + 1);
    float4 b2 = ldg_cs4(gm + q0 + 2), b3 = ldg_cs4(gm + q0 + 3);

    #define EMIT8(ca, cb, idx8) { \
        float o0, o1, o2, o3, o4, o5, o6, o7; \
        nf = nf_step(ca.x, nf, rise, fall, fl); o0 = __fdividef(ca.x, fmaf(ns10, nf, 1e-7f)); \
        nf = nf_step(ca.y, nf, rise, fall, fl); o1 = __fdividef(ca.y, fmaf(ns10, nf, 1e-7f)); \
        nf = nf_step(ca.z, nf, rise, fall, fl); o2 = __fdividef(ca.z, fmaf(ns10, nf, 1e-7f)); \
        nf = nf_step(ca.w, nf, rise, fall, fl); o3 = __fdividef(ca.w, fmaf(ns10, nf, 1e-7f)); \
        nf = nf_step(cb.x, nf, rise, fall, fl); o4 = __fdividef(cb.x, fmaf(ns10, nf, 1e-7f)); \
        nf = nf_step(cb.y, nf, rise, fall, fl); o5 = __fdividef(cb.y, fmaf(ns10, nf, 1e-7f)); \
        nf = nf_step(cb.z, nf, rise, fall, fl); o6 = __fdividef(cb.z, fmaf(ns10, nf, 1e-7f)); \
        nf = nf_step(cb.w, nf, rise, fall, fl); o7 = __fdividef(cb.w, fmaf(ns10, nf, 1e-7f)); \
        H8 pk; \
        pk.a = __floats2half2_rn(o0, o1); pk.b = __floats2half2_rn(o2, o3); \
        pk.c = __floats2half2_rn(o4, o5); pk.d = __floats2half2_rn(o6, o7); \
        gv8[idx8] = pk; }

    for (int i = 0; i < CHUNK / 4; i += 4) {
        float4 c0 = b0, c1 = b1, c2 = b2, c3 = b3;
        if (i + 8 <= CHUNK / 4) {
            b0 = ldg_cs4(gm + q0 + i + 4); b1 = ldg_cs4(gm + q0 + i + 5);
            b2 = ldg_cs4(gm + q0 + i + 6); b3 = ldg_cs4(gm + q0 + i + 7);
        }
        EMIT8(c0, c1, (q0 + i) >> 1);
        EMIT8(c2, c3, ((q0 + i) >> 1) + 1);
    }
    #undef EMIT8
}

// ============================================================
// K2: HMMA band GEMM, two-group cp.async pipeline (k 0..8 | k 9..16)
// ============================================================
extern __shared__ char k2_smem[];

__global__ __launch_bounds__(256, 2) void band_kernel(float* __restrict__ out)
{
    const int b   = blockIdx.y;
    const int t0  = blockIdx.x * TTILE;
    const int tid = threadIdx.x;
    const int wid = tid >> 5;
    const int lane = tid & 31;

    __half* As = reinterpret_cast<__half*>(k2_smem);             // [FPAD][AST]
    __half* Bs = reinterpret_cast<__half*>(k2_smem + A_BYTES);   // [NBn][BST]
    const uint32_t As_u = smem_u32(As);
    const uint32_t Bs_u = smem_u32(Bs);

    const size_t vbase = (size_t)b * Fn * Tn;
    // group 1: A rows f < KSPLIT*16 (=144) + full B tile
    #pragma unroll
    for (int it = 0; it < 9; ++it) {                 // 144*16/256 = 9
        int i = tid + it * 256;
        int f = i >> 4;
        int c = i & 15;
        int t = t0 + c * 8;
        int sz = (f < Fn && t + 8 <= Tn) ? 16 : 0;
        int tc = (t + 8 <= Tn) ? t : 0;
        cpasync16(As_u + (uint32_t)((f * AST + c * 8) * 2),
                  g_vnr + vbase + (size_t)f * Tn + tc, sz);
    }
    #pragma unroll
    for (int it = 0; it < 9; ++it) {
        int i = tid + it * 256;
        if (i < NBn * BST / 8)
            cpasync16(Bs_u + (uint32_t)(i * 16), g_fbh + i * 8, 16);
    }
    cp_commit();
    // group 2: A rows f in [144, 272)
    #pragma unroll
    for (int it = 0; it < 8; ++it) {                 // 128*16/256 = 8
        int i = tid + it * 256 + 144 * 16;
        int f = i >> 4;
        int c = i & 15;
        int t = t0 + c * 8;
        int sz = (f < Fn && t + 8 <= Tn) ? 16 : 0;
        int fc = (f < Fn) ? f : 0;
        int tc = (t + 8 <= Tn) ? t : 0;
        cpasync16(As_u + (uint32_t)((f * AST + c * 8) * 2),
                  g_vnr + vbase + (size_t)fc * Tn + tc, sz);
    }
    cp_commit();

    const int m0 = wid * 16;
    const int krow = (lane & 7) + ((lane >> 4) << 3);
    const int msel = ((lane >> 3) & 1) * 8;
    const uint32_t a_addr0 = As_u + (uint32_t)((krow * AST + m0 + msel) * 2);

    const int nrow = (lane & 7) + ((lane >> 4) << 3);
    const int ksel = ((lane >> 3) & 1) * 8;
    uint32_t b_addr0[4];
    #pragma unroll
    for (int j2 = 0; j2 < 4; ++j2)
        b_addr0[j2] = Bs_u + (uint32_t)(((j2 * 16 + nrow) * BST + ksel) * 2);

    float d[8][4];
    #pragma unroll
    for (int j = 0; j < 8; ++j)
        #pragma unroll
        for (int q = 0; q < 4; ++q) d[j][q] = 0.0f;

    cp_wait1();
    __syncthreads();

    for (int ks = 0; ks < KSPLIT; ++ks) {
        uint32_t a[4];
        ldsm_x4_t(a, a_addr0 + (uint32_t)(ks * 16 * AST * 2));
        #pragma unroll
        for (int j2 = 0; j2 < 4; ++j2) {
            uint32_t bbv[4];
            ldsm_x4(bbv, b_addr0[j2] + (uint32_t)(ks * 32));
            mma16816(d[j2 * 2],     a, bbv[0], bbv[1]);
            mma16816(d[j2 * 2 + 1], a, bbv[2], bbv[3]);
        }
    }

    cp_wait0();
    __syncthreads();

    for (int ks = KSPLIT; ks < KSTEPS; ++ks) {
        uint32_t a[4];
        ldsm_x4_t(a, a_addr0 + (uint32_t)(ks * 16 * AST * 2));
        #pragma unroll
        for (int j2 = 0; j2 < 4; ++j2) {
            uint32_t bbv[4];
            ldsm_x4(bbv, b_addr0[j2] + (uint32_t)(ks * 32));
            mma16816(d[j2 * 2],     a, bbv[0], bbv[1]);
            mma16816(d[j2 * 2 + 1], a, bbv[2], bbv[3]);
        }
    }

    __syncthreads();
    float* stg = reinterpret_cast<float*>(k2_smem);              // [NBn][OST]
    const int g  = lane >> 2;
    const int tp = lane & 3;
    #pragma unroll
    for (int j = 0; j < 8; ++j) {
        int n = j * 8 + 2 * tp;
        int t = m0 + g;
        stg[n * OST + t]           = d[j][0];
        stg[(n + 1) * OST + t]     = d[j][1];
        stg[n * OST + t + 8]       = d[j][2];
        stg[(n + 1) * OST + t + 8] = d[j][3];
    }
    __syncthreads();

    const int tmax = Tn - t0;
    float* ob = out + (size_t)b * NBn * Tn + t0;
    #pragma unroll
    for (int it = 0; it < 8; ++it) {
        int idx = tid + it * 256;
        int n = idx >> 5;
        int c = (idx & 31) * 4;
        if (c < tmax) {
            float4 v = *reinterpret_cast<float4*>(stg + n * OST + c);
            v.x = tanh_fast(v.x); v.y = tanh_fast(v.y);
            v.z = tanh_fast(v.z); v.w = tanh_fast(v.w);
            *reinterpret_cast<float4*>(ob + (size_t)n * Tn + c) = v;
        }
    }
}

// ============================================================
extern "C" void kernel_launch(void* const* d_in, const int* in_sizes, int n_in,
                              void* d_out, int out_size)
{
    const float* mag = (const float*)d_in[0];
    const float* fb  = (const float*)d_in[1];
    const float* ns  = (const float*)d_in[2];
    const float* rr  = (const float*)d_in[3];
    const float* rf  = (const float*)d_in[4];
    float* out = (float*)d_out;

    cudaFuncSetAttribute(band_kernel, cudaFuncAttributeMaxDynamicSharedMemorySize, SMEM_TOTAL);

    scan_kernel<<<SCAN_BLOCKS + 8, 256>>>(mag, fb, ns, rr, rf);

    dim3 grid((Tn + TTILE - 1) / TTILE, Bn);   // 63 x 16
    band_kernel<<<grid, 256, SMEM_TOTAL>>>(out);
}

// round 14
// speedup vs baseline: 1.7128x; 1.1238x over previous
#include <cuda_runtime.h>
#include <cuda_fp16.h>
#include <cstdint>

#define Bn 16
#define Fn 257
#define FPAD 272
#define Tn 8000
#define NBn 64
#define TTILE 128
#define KSTEPS 17

// ---- staged scan v3 config ----
#define NCH 8
#define CHUNK 1000
#define WARM 128
#define LOCAL (WARM + CHUNK)          // 1128
#define STILE 64
#define NTILE 18                      // 18*64 = 1152 >= LOCAL
#define ROWST 68                      // floats (272 B): LDS.128 conflict-free
#define O2ST 33                       // words: odd -> conflict-free half2 staging
#define WBUF (32 * ROWST)             // 2176 floats
#define O2OFF (8 * 2 * WBUF)          // 34816 floats
#define SCAN_SMEM ((O2OFF + 8 * 32 * O2ST) * 4)   // 173056 B
#define SCAN_GRID (Bn * 9)            // 144

// ---- band GEMM config ----
#define AST 136
#define BST 280
#define OST 132
#define A_BYTES (FPAD * AST * 2)
#define B_BYTES (NBn * BST * 2)
#define SMEM_TOTAL (A_BYTES + B_BYTES)
#define KSPLIT 9

// 65.8 MB fp16 scratch: g_vnr[b][f][t] = vnr/10 (t-contiguous)
__device__ __align__(128) __half g_vnr[(size_t)Bn * Fn * Tn];
__device__ __align__(128) __half g_fbh[NBn * BST];

__device__ __forceinline__ uint32_t smem_u32(const void* p) {
    uint32_t a;
    asm("{ .reg .u64 t; cvta.to.shared.u64 t, %1; cvt.u32.u64 %0, t; }" : "=r"(a) : "l"(p));
    return a;
}
__device__ __forceinline__ void cpasync16(uint32_t dst, const void* src, int sz) {
    asm volatile("cp.async.ca.shared.global [%0], [%1], 16, %2;" :: "r"(dst), "l"(src), "r"(sz));
}
__device__ __forceinline__ void cp_commit() { asm volatile("cp.async.commit_group;" ::: "memory"); }
__device__ __forceinline__ void cp_wait0()  { asm volatile("cp.async.wait_group 0;" ::: "memory"); }
__device__ __forceinline__ void cp_wait1()  { asm volatile("cp.async.wait_group 1;" ::: "memory"); }

__device__ __forceinline__ void ldsm_x4_t(uint32_t a[4], uint32_t addr) {
    asm volatile("ldmatrix.sync.aligned.m8n8.x4.trans.shared.b16 {%0,%1,%2,%3}, [%4];"
        : "=r"(a[0]), "=r"(a[1]), "=r"(a[2]), "=r"(a[3]) : "r"(addr));
}
__device__ __forceinline__ void ldsm_x4(uint32_t a[4], uint32_t addr) {
    asm volatile("ldmatrix.sync.aligned.m8n8.x4.shared.b16 {%0,%1,%2,%3}, [%4];"
        : "=r"(a[0]), "=r"(a[1]), "=r"(a[2]), "=r"(a[3]) : "r"(addr));
}
__device__ __forceinline__ void mma16816(float d[4], const uint32_t a[4], uint32_t b0, uint32_t b1) {
    asm volatile("mma.sync.aligned.m16n8k16.row.col.f32.f16.f16.f32 "
        "{%0,%1,%2,%3}, {%4,%5,%6,%7}, {%8,%9}, {%0,%1,%2,%3};"
        : "+f"(d[0]), "+f"(d[1]), "+f"(d[2]), "+f"(d[3])
        : "r"(a[0]), "r"(a[1]), "r"(a[2]), "r"(a[3]), "r"(b0), "r"(b1));
}
__device__ __forceinline__ float tanh_fast(float x) {
    float y; asm("tanh.approx.f32 %0, %1;" : "=f"(y) : "f"(x)); return y;
}

__device__ __forceinline__ float nf_step(float x, float nf, float rise, float fall, float fl) {
    float d  = x - nf;
    float cr = fmaf(rise, d, nf);
    float cf = fmaf(fall, d, nf);
    return fmaxf(fmaxf(cr, cf), fl);
}

// ============================================================
// K1: staged scan v3 -> g_vnr fp16 (vnr/10)
// Block = 32 chains (b, fg) x 8 chunk-warps. Coalesced cp.async.16
// tile loads (depth-2, wait_group 1), conflict-free LDS.128 reads,
// conflict-free half2 output staging, coalesced flush. No block syncs.
// Blocks >= SCAN_GRID: fused fb conversion.
// ============================================================
extern __shared__ float s_scan[];

__global__ __launch_bounds__(256, 1) void scan_kernel(
    const float* __restrict__ mag,
    const float* __restrict__ fbw,
    const float* __restrict__ p_ns,
    const float* __restrict__ p_rr,
    const float* __restrict__ p_rf)
{
    if (blockIdx.x >= SCAN_GRID) {
        int base = (blockIdx.x - SCAN_GRID) * 256 + threadIdx.x;
        for (int i = base; i < NBn * BST; i += 256 * 8) {
            int n = i / BST;
            int f = i - n * BST;
            g_fbh[i] = (f < Fn) ? __float2half_rn(__ldg(fbw + n * Fn + f)) : __float2half_rn(0.0f);
        }
        return;
    }

    const int bb = blockIdx.x / 9;
    const int fg = blockIdx.x % 9;
    const int c  = threadIdx.x >> 5;   // chunk (warp)
    const int l  = threadIdx.x & 31;   // chain lane

    const uint32_t sbase = smem_u32(s_scan);

    const float rise = 1.0f / (1.0f + expf(-__ldg(p_rr)));
    const float fall = 1.0f / (1.0f + expf(-__ldg(p_rf)));
    const float ns10 = 10.0f * fabsf(__ldg(p_ns));

    const int fmine = fg * 32 + l;
    const bool fvalid = (fmine < Fn);
    const size_t myrow = ((size_t)bb * Fn + (fvalid ? fmine : 0)) * Tn;

    // init min over first 20 frames: 5 x LDG.128 (single line per lane)
    const float4* ir = reinterpret_cast<const float4*>(mag + myrow);
    float4 a0 = __ldg(ir), a1 = __ldg(ir + 1), a2 = __ldg(ir + 2),
           a3 = __ldg(ir + 3), a4 = __ldg(ir + 4);
    float mn = fminf(fminf(fminf(a0.x, a0.y), fminf(a0.z, a0.w)),
               fminf(fminf(fminf(a1.x, a1.y), fminf(a1.z, a1.w)),
               fminf(fminf(fminf(a2.x, a2.y), fminf(a2.z, a2.w)),
               fminf(fminf(fminf(a3.x, a3.y), fminf(a3.z, a3.w)),
                     fminf(fminf(a4.x, a4.y), fminf(a4.z, a4.w))))));
    mn = fmaxf(mn, 1e-5f);
    const float fl_ = 0.5f * mn;
    float nf = mn;

    const int t0base = c * CHUNK - WARM;
    const float* magb = mag + (size_t)bb * Fn * Tn;

    #define ISSUE(k, sel) { \
        const int t0g = t0base + (k) * STILE; \
        const uint32_t dbase = sbase + (uint32_t)((c * 2 + (sel)) * WBUF * 4); \
        _Pragma("unroll") \
        for (int it = 0; it < 16; ++it) { \
            int o = l + 32 * it; \
            int m = o >> 4; \
            int seg = o & 15; \
            int tt = t0g + seg * 4; \
            int fm = fg * 32 + m; \
            int sz = (tt >= 0 && tt + 4 <= Tn && fm < Fn) ? 16 : 0; \
            int ttc = (tt < 0) ? 0 : ((tt + 4 > Tn) ? (Tn - 4) : tt); \
            int fmc = (fm < Fn) ? fm : 0; \
            cpasync16(dbase + (uint32_t)((m * ROWST + seg * 4) * 4), \
                      magb + (size_t)fmc * Tn + ttc, sz); \
        } \
        cp_commit(); }

    ISSUE(0, 0);
    ISSUE(1, 1);

    for (int k = 0; k < NTILE; ++k) {
        cp_wait1();
        __syncwarp();

        const float4* srow4 = reinterpret_cast<const float4*>(
            s_scan + (c * 2 + (k & 1)) * WBUF + l * ROWST);
        float* orow = s_scan + O2OFF + (c * 32 + l) * O2ST;

        const bool live = (c > 0 || k >= 2);   // c==0 starts at i=WARM (tile 2)
        const bool outp = (k >= 2);            // outputs exist iff i >= WARM

        if (live) {
            #pragma unroll
            for (int j4 = 0; j4 < 16; ++j4) {
                const int i = k * STILE + j4 * 4;
                if (i < LOCAL) {
                    float4 v = srow4[j4];        // conflict-free LDS.128
                    float o0, o1, o2, o3;
                    nf = nf_step(v.x, nf, rise, fall, fl_); o0 = __fdividef(v.x, fmaf(ns10, nf, 1e-7f));
                    nf = nf_step(v.y, nf, rise, fall, fl_); o1 = __fdividef(v.y, fmaf(ns10, nf, 1e-7f));
                    nf = nf_step(v.z, nf, rise, fall, fl_); o2 = __fdividef(v.z, fmaf(ns10, nf, 1e-7f));
                    nf = nf_step(v.w, nf, rise, fall, fl_); o3 = __fdividef(v.w, fmaf(ns10, nf, 1e-7f));
                    if (outp) {
                        __half2 h0 = __floats2half2_rn(o0, o1);
                        __half2 h1 = __floats2half2_rn(o2, o3);
                        *reinterpret_cast<__half2*>(&orow[j4 * 2])     = h0;
                        *reinterpret_cast<__half2*>(&orow[j4 * 2 + 1]) = h1;
                    }
                }
            }
        }
        __syncwarp();

        if (outp) {
            const int tg = c * CHUNK + (k - 2) * STILE;
            const int nh = (((k + 1) * STILE < LOCAL ? (k + 1) * STILE : LOCAL) - k * STILE) >> 1;
            #pragma unroll
            for (int m = 0; m < 32; ++m) {
                const int fm = fg * 32 + m;
                if (fm < Fn && l < nh) {
                    float w = s_scan[O2OFF + (c * 32 + m) * O2ST + l];
                    *reinterpret_cast<__half2*>(
                        g_vnr + ((size_t)bb * Fn + fm) * Tn + tg + 2 * l) =
                        *reinterpret_cast<__half2*>(&w);
                }
            }
        }
        __syncwarp();

        if (k + 2 < NTILE) ISSUE(k + 2, k & 1);
    }
    cp_wait0();
    #undef ISSUE
}

// ============================================================
// K2: HMMA band GEMM (r13 version, 29.9us)
// ============================================================
extern __shared__ char k2_smem[];

__global__ __launch_bounds__(256, 2) void band_kernel(float* __restrict__ out)
{
    const int b   = blockIdx.y;
    const int t0  = blockIdx.x * TTILE;
    const int tid = threadIdx.x;
    const int wid = tid >> 5;
    const int lane = tid & 31;

    __half* As = reinterpret_cast<__half*>(k2_smem);             // [FPAD][AST]
    __half* Bs = reinterpret_cast<__half*>(k2_smem + A_BYTES);   // [NBn][BST]
    const uint32_t As_u = smem_u32(As);
    const uint32_t Bs_u = smem_u32(Bs);

    const size_t vbase = (size_t)b * Fn * Tn;
    #pragma unroll
    for (int it = 0; it < 9; ++it) {                 // A rows f < 144
        int i = tid + it * 256;
        int f = i >> 4;
        int c = i & 15;
        int t = t0 + c * 8;
        int sz = (f < Fn && t + 8 <= Tn) ? 16 : 0;
        int tc = (t + 8 <= Tn) ? t : 0;
        cpasync16(As_u + (uint32_t)((f * AST + c * 8) * 2),
                  g_vnr + vbase + (size_t)f * Tn + tc, sz);
    }
    #pragma unroll
    for (int it = 0; it < 9; ++it) {
        int i = tid + it * 256;
        if (i < NBn * BST / 8)
            cpasync16(Bs_u + (uint32_t)(i * 16), g_fbh + i * 8, 16);
    }
    cp_commit();
    #pragma unroll
    for (int it = 0; it < 8; ++it) {                 // A rows f in [144, 272)
        int i = tid + it * 256 + 144 * 16;
        int f = i >> 4;
        int c = i & 15;
        int t = t0 + c * 8;
        int sz = (f < Fn && t + 8 <= Tn) ? 16 : 0;
        int fc = (f < Fn) ? f : 0;
        int tc = (t + 8 <= Tn) ? t : 0;
        cpasync16(As_u + (uint32_t)((f * AST + c * 8) * 2),
                  g_vnr + vbase + (size_t)fc * Tn + tc, sz);
    }
    cp_commit();

    const int m0 = wid * 16;
    const int krow = (lane & 7) + ((lane >> 4) << 3);
    const int msel = ((lane >> 3) & 1) * 8;
    const uint32_t a_addr0 = As_u + (uint32_t)((krow * AST + m0 + msel) * 2);

    const int nrow = (lane & 7) + ((lane >> 4) << 3);
    const int ksel = ((lane >> 3) & 1) * 8;
    uint32_t b_addr0[4];
    #pragma unroll
    for (int j2 = 0; j2 < 4; ++j2)
        b_addr0[j2] = Bs_u + (uint32_t)(((j2 * 16 + nrow) * BST + ksel) * 2);

    float d[8][4];
    #pragma unroll
    for (int j = 0; j < 8; ++j)
        #pragma unroll
        for (int q = 0; q < 4; ++q) d[j][q] = 0.0f;

    cp_wait1();
    __syncthreads();

    for (int ks = 0; ks < KSPLIT; ++ks) {
        uint32_t a[4];
        ldsm_x4_t(a, a_addr0 + (uint32_t)(ks * 16 * AST * 2));
        #pragma unroll
        for (int j2 = 0; j2 < 4; ++j2) {
            uint32_t bbv[4];
            ldsm_x4(bbv, b_addr0[j2] + (uint32_t)(ks * 32));
            mma16816(d[j2 * 2],     a, bbv[0], bbv[1]);
            mma16816(d[j2 * 2 + 1], a, bbv[2], bbv[3]);
        }
    }

    cp_wait0();
    __syncthreads();

    for (int ks = KSPLIT; ks < KSTEPS; ++ks) {
        uint32_t a[4];
        ldsm_x4_t(a, a_addr0 + (uint32_t)(ks * 16 * AST * 2));
        #pragma unroll
        for (int j2 = 0; j2 < 4; ++j2) {
            uint32_t bbv[4];
            ldsm_x4(bbv, b_addr0[j2] + (uint32_t)(ks * 32));
            mma16816(d[j2 * 2],     a, bbv[0], bbv[1]);
            mma16816(d[j2 * 2 + 1], a, bbv[2], bbv[3]);
        }
    }

    __syncthreads();
    float* stg = reinterpret_cast<float*>(k2_smem);              // [NBn][OST]
    const int g  = lane >> 2;
    const int tp = lane & 3;
    #pragma unroll
    for (int j = 0; j < 8; ++j) {
        int n = j * 8 + 2 * tp;
        int t = m0 + g;
        stg[n * OST + t]           = d[j][0];
        stg[(n + 1) * OST + t]     = d[j][1];
        stg[n * OST + t + 8]       = d[j][2];
        stg[(n + 1) * OST + t + 8] = d[j][3];
    }
    __syncthreads();

    const int tmax = Tn - t0;
    float* ob = out + (size_t)b * NBn * Tn + t0;
    #pragma unroll
    for (int it = 0; it < 8; ++it) {
        int idx = tid + it * 256;
        int n = idx >> 5;
        int c = (idx & 31) * 4;
        if (c < tmax) {
            float4 v = *reinterpret_cast<float4*>(stg + n * OST + c);
            v.x = tanh_fast(v.x); v.y = tanh_fast(v.y);
            v.z = tanh_fast(v.z); v.w = tanh_fast(v.w);
            *reinterpret_cast<float4*>(ob + (size_t)n * Tn + c) = v;
        }
    }
}

// ============================================================
extern "C" void kernel_launch(void* const* d_in, const int* in_sizes, int n_in,
                              void* d_out, int out_size)
{
    const float* mag = (const float*)d_in[0];
    const float* fb  = (const float*)d_in[1];
    const float* ns  = (const float*)d_in[2];
    const float* rr  = (const float*)d_in[3];
    const float* rf  = (const float*)d_in[4];
    float* out = (float*)d_out;

    cudaFuncSetAttribute(scan_kernel, cudaFuncAttributeMaxDynamicSharedMemorySize, SCAN_SMEM);
    cudaFuncSetAttribute(band_kernel, cudaFuncAttributeMaxDynamicSharedMemorySize, SMEM_TOTAL);

    scan_kernel<<<SCAN_GRID + 8, 256, SCAN_SMEM>>>(mag, fb, ns, rr, rf);

    dim3 grid((Tn + TTILE - 1) / TTILE, Bn);   // 63 x 16
    band_kernel<<<grid, 256, SMEM_TOTAL>>>(out);
}